// round 5
// baseline (speedup 1.0000x reference)
#include <cuda_runtime.h>
#include <math.h>

// Problem dims
#define TT 256     // time steps
#define BB 256     // batch
#define HH 1024    // hidden
#define N2 2048    // 2*HH

// Tile config
#define BM 64
#define BJ 32
#define KT 16
#define NTHR 256
#define GBLK 256   // persistent grid size (<= 2 blocks/SM * 148 SMs = 296)

// State buffers s0..s8
__device__ float g_S[9][BB * HH];
__device__ unsigned long long g_bar;   // monotonic grid-barrier counter

typedef unsigned long long u64;

__device__ __forceinline__ float sigf(float v) { return 1.0f / (1.0f + expf(-v)); }

__device__ __forceinline__ float actf(float v, int a) {
    switch (a) {
        case 0: return sigf(v);
        case 1: return fmaxf(v, 0.0f);
        case 2: return tanhf(v);
        default: return v;  // identity
    }
}

// ---- packed f32x2 helpers (sm_103a) ----
__device__ __forceinline__ void fma2(u64& acc, u64 a, u64 b) {
    asm("fma.rn.f32x2 %0, %1, %2, %0;" : "+l"(acc) : "l"(a), "l"(b));
}
__device__ __forceinline__ u64 pack2(float x) {
    u64 r;
    asm("mov.b64 %0, {%1, %1};" : "=l"(r) : "f"(x));
    return r;
}
__device__ __forceinline__ float2 unpk(u64 v) {
    float2 r;
    asm("mov.b64 {%0, %1}, %2;" : "=f"(r.x), "=f"(r.y) : "l"(v));
    return r;
}

// ---- software grid barrier (monotonic ticket; safe across graph replays) ----
__device__ __forceinline__ void gridbar() {
    __threadfence();
    __syncthreads();
    if (threadIdx.x == 0) {
        u64 t = atomicAdd(&g_bar, 1ULL);
        u64 goal = (t / GBLK + 1ULL) * (u64)GBLK;
        u64 v;
        do {
            asm volatile("ld.acquire.gpu.u64 %0, [%1];" : "=l"(v) : "l"(&g_bar) : "memory");
        } while (v < goal);
    }
    __syncthreads();
}

// ---- fused GEMM tile + DARTS epilogue ----
// Tile: BM x BJ of output columns j in [0,1024), computing both halves
// (c at col j, h at col j+1024) of A @ W, then
//   s[m,j] = sp[m,j] + sigmoid(c) * (act(h) - sp[m,j])
// CONCAT: A = concat(xA, xB) over K=2048 (xB = h_prev = Sprev). Else K=1024, Sprev = A.
template <bool CONCAT>
__device__ __noinline__ void gemm_tile(
    const float* __restrict__ xA, const float* __restrict__ xB,
    const float* __restrict__ W, const float* __restrict__ Sprev,
    float* __restrict__ Sout, int act, int tileIdx,
    float (&AsT)[KT][BM + 2], float (&Wcs)[KT][BJ], float (&Whs)[KT][BJ])
{
    const int K = CONCAT ? N2 : HH;
    const int m0 = (tileIdx & 3) * BM;       // 4 m-tiles
    const int j0 = (tileIdx >> 2) * BJ;      // 32 j-tiles
    const int tid = threadIdx.x;

    // A loader: thread -> (row mA, 4 consecutive k), stored transposed [k][m]
    const int mA = tid >> 2;
    const int kq = (tid & 3) << 2;
    // W loader: 128 threads for c-half, 128 for h-half
    const int wHalf = tid >> 7;
    const int wt = tid & 127;
    const int kkW = wt >> 3;
    const int jq = (wt & 7) << 2;
    // Compute map: 16 rowgroups (4 rows each) x 16 colgroups (2 cols each)
    const int r0 = (tid >> 4) << 2;
    const int jj = (tid & 15) << 1;

    u64 accC[2][2] = {{0ULL, 0ULL}, {0ULL, 0ULL}};   // [rowpair][col], lanes = 2 rows
    u64 accH[2][2] = {{0ULL, 0ULL}, {0ULL, 0ULL}};

    auto ldA = [&](int kc) -> float4 {
        int col = kc + kq;
        const float* base = xA;
        int cc = col;
        if (CONCAT && col >= HH) { base = xB; cc = col - HH; }
        return *reinterpret_cast<const float4*>(base + (size_t)(m0 + mA) * HH + cc);
    };
    auto ldW = [&](int kc) -> float4 {
        return *reinterpret_cast<const float4*>(
            W + (size_t)(kc + kkW) * N2 + wHalf * HH + j0 + jq);
    };

    float4 pa = ldA(0);
    float4 pw = ldW(0);

    for (int kc = 0; kc < K; kc += KT) {
        __syncthreads();
        AsT[kq + 0][mA] = pa.x;
        AsT[kq + 1][mA] = pa.y;
        AsT[kq + 2][mA] = pa.z;
        AsT[kq + 3][mA] = pa.w;
        if (wHalf == 0) *reinterpret_cast<float4*>(&Wcs[kkW][jq]) = pw;
        else            *reinterpret_cast<float4*>(&Whs[kkW][jq]) = pw;
        __syncthreads();
        if (kc + KT < K) { pa = ldA(kc + KT); pw = ldW(kc + KT); }

#pragma unroll
        for (int kk = 0; kk < KT; kk++) {
            u64 a01 = *reinterpret_cast<const u64*>(&AsT[kk][r0]);       // rows r0,r0+1
            u64 a23 = *reinterpret_cast<const u64*>(&AsT[kk][r0 + 2]);   // rows r0+2,r0+3
            float2 wc = *reinterpret_cast<const float2*>(&Wcs[kk][jj]);
            float2 wh = *reinterpret_cast<const float2*>(&Whs[kk][jj]);
            u64 wcx = pack2(wc.x), wcy = pack2(wc.y);
            u64 whx = pack2(wh.x), why = pack2(wh.y);
            fma2(accC[0][0], a01, wcx); fma2(accC[1][0], a23, wcx);
            fma2(accC[0][1], a01, wcy); fma2(accC[1][1], a23, wcy);
            fma2(accH[0][0], a01, whx); fma2(accH[1][0], a23, whx);
            fma2(accH[0][1], a01, why); fma2(accH[1][1], a23, why);
        }
    }

#pragma unroll
    for (int p = 0; p < 2; p++) {
        float2 c0 = unpk(accC[p][0]), c1 = unpk(accC[p][1]);
        float2 h0v = unpk(accH[p][0]), h1v = unpk(accH[p][1]);
#pragma unroll
        for (int l = 0; l < 2; l++) {
            int m = m0 + r0 + 2 * p + l;
            float cc0 = l ? c0.y : c0.x;
            float cc1 = l ? c1.y : c1.x;
            float hh0 = l ? h0v.y : h0v.x;
            float hh1 = l ? h1v.y : h1v.x;
            float2 sp = *reinterpret_cast<const float2*>(Sprev + (size_t)m * HH + j0 + jj);
            float s0v = sp.x + sigf(cc0) * (actf(hh0, act) - sp.x);
            float s1v = sp.y + sigf(cc1) * (actf(hh1, act) - sp.y);
            *reinterpret_cast<float2*>(Sout + (size_t)m * HH + j0 + jj) = make_float2(s0v, s1v);
        }
    }
}

// ---- single persistent kernel: all T steps, all ops ----
__global__ __launch_bounds__(NTHR, 2) void darts_persist(
    const float* __restrict__ inputs,  // [T, B, 1024]
    const float* __restrict__ h0,      // [B, 1024]
    const float* __restrict__ W0,      // [2048, 2048]
    const float* __restrict__ Ws,      // [8, 1024, 2048]
    float* __restrict__ out)           // [T, B, 1024]
{
    __shared__ __align__(16) float AsT[KT][BM + 2];
    __shared__ __align__(16) float Wcs[KT][BJ];
    __shared__ __align__(16) float Whs[KT][BJ];

    const int bid = blockIdx.x;
    const size_t WSTR = (size_t)HH * N2;

    for (int t = 0; t < TT; t++) {
        const float* xt = inputs + (size_t)t * BB * HH;
        const float* hp = t ? (out + (size_t)(t - 1) * BB * HH) : h0;

        // Phase A: s0 = h + sig(c0)*(tanh(h0c)-h), K=2048 concat(x, h_prev)
        for (int it = bid; it < 128; it += GBLK)
            gemm_tile<true>(xt, hp, W0, hp, g_S[0], 2, it, AsT, Wcs, Whs);
        gridbar();

        // Phase B: s1 = f(s0, Ws[0], sigmoid)
        for (int it = bid; it < 128; it += GBLK)
            gemm_tile<false>(g_S[0], nullptr, Ws + 0 * WSTR, g_S[0], g_S[1], 0, it, AsT, Wcs, Whs);
        gridbar();

        // Phase C: s2=f(s1,Ws1,relu), s3=f(s1,Ws2,relu), s4=f(s1,Ws3,id)
        for (int it = bid; it < 384; it += GBLK) {
            int op = it >> 7, ti = it & 127;
            gemm_tile<false>(g_S[1], nullptr, Ws + (size_t)(1 + op) * WSTR,
                             g_S[1], g_S[2 + op], (op == 2) ? 3 : 1, ti, AsT, Wcs, Whs);
        }
        gridbar();

        // Phase D: s5=f(s2,Ws4,tanh), s7=f(s3,Ws6,tanh)
        for (int it = bid; it < 256; it += GBLK) {
            int op = it >> 7, ti = it & 127;
            const float* Ap = op ? g_S[3] : g_S[2];
            const float* Wp = Ws + (size_t)(op ? 6 : 4) * WSTR;
            float* Op = op ? g_S[7] : g_S[5];
            gemm_tile<false>(Ap, nullptr, Wp, Ap, Op, 2, ti, AsT, Wcs, Whs);
        }
        gridbar();

        // Phase E: s6=f(s5,Ws5,sigmoid), s8=f(s5,Ws7,relu)
        for (int it = bid; it < 256; it += GBLK) {
            int op = it >> 7, ti = it & 127;
            const float* Wp = Ws + (size_t)(op ? 7 : 5) * WSTR;
            float* Op = op ? g_S[8] : g_S[6];
            gemm_tile<false>(g_S[5], nullptr, Wp, g_S[5], Op, op ? 1 : 0, ti, AsT, Wcs, Whs);
        }
        gridbar();

        // Phase F: out[t] = mean(s1..s8)
        {
            float* ot = out + (size_t)t * BB * HH;
            for (int i = bid * NTHR + threadIdx.x; i < BB * HH / 4; i += GBLK * NTHR) {
                float4 s = make_float4(0.f, 0.f, 0.f, 0.f);
#pragma unroll
                for (int b = 1; b < 9; b++) {
                    float4 v = reinterpret_cast<const float4*>(g_S[b])[i];
                    s.x += v.x; s.y += v.y; s.z += v.z; s.w += v.w;
                }
                reinterpret_cast<float4*>(ot)[i] =
                    make_float4(s.x * 0.125f, s.y * 0.125f, s.z * 0.125f, s.w * 0.125f);
            }
        }
        gridbar();
    }
}

extern "C" void kernel_launch(void* const* d_in, const int* in_sizes, int n_in,
                              void* d_out, int out_size)
{
    const float* inputs = (const float*)d_in[0];  // [T, B, 1024]
    const float* h0     = (const float*)d_in[1];  // [B, 1024]
    const float* W0     = (const float*)d_in[2];  // [2048, 2048]
    const float* Ws     = (const float*)d_in[3];  // [8, 1024, 2048]
    float* out = (float*)d_out;                   // [T, B, 1024]

    darts_persist<<<GBLK, NTHR>>>(inputs, h0, W0, Ws, out);
}

// round 6
// speedup vs baseline: 1.0248x; 1.0248x over previous
#include <cuda_runtime.h>
#include <math.h>

// Problem dims
#define TT 256     // time steps
#define BB 256     // batch
#define HH 1024    // hidden
#define N2 2048    // 2*HH

// Tile config
#define BM 64
#define BJ 32
#define KT 16
#define NTHR 256
#define GBLK 256   // persistent grid size (<= 2 blocks/SM * 148 SMs = 296)

// State buffers s0..s8
__device__ float g_S[9][BB * HH];
__device__ unsigned long long g_bar;   // monotonic grid-barrier counter

typedef unsigned long long u64;

__device__ __forceinline__ float sigf(float v) { return 1.0f / (1.0f + expf(-v)); }

__device__ __forceinline__ float actf(float v, int a) {
    switch (a) {
        case 0: return sigf(v);
        case 1: return fmaxf(v, 0.0f);
        case 2: return tanhf(v);
        default: return v;  // identity
    }
}

// ---- packed f32x2 helpers (sm_103a) ----
__device__ __forceinline__ void fma2(u64& acc, u64 a, u64 b) {
    asm("fma.rn.f32x2 %0, %1, %2, %0;" : "+l"(acc) : "l"(a), "l"(b));
}
__device__ __forceinline__ u64 pack2(float x) {
    u64 r;
    asm("mov.b64 %0, {%1, %1};" : "=l"(r) : "f"(x));
    return r;
}
__device__ __forceinline__ float2 unpk(u64 v) {
    float2 r;
    asm("mov.b64 {%0, %1}, %2;" : "=f"(r.x), "=f"(r.y) : "l"(v));
    return r;
}

// ---- software grid barrier (monotonic ticket; safe across graph replays) ----
__device__ __forceinline__ void gridbar() {
    __threadfence();
    __syncthreads();
    if (threadIdx.x == 0) {
        u64 t = atomicAdd(&g_bar, 1ULL);
        u64 goal = (t / GBLK + 1ULL) * (u64)GBLK;
        u64 v;
        do {
            asm volatile("ld.acquire.gpu.u64 %0, [%1];" : "=l"(v) : "l"(&g_bar) : "memory");
        } while (v < goal);
    }
    __syncthreads();
}

// ---- fused GEMM tile + DARTS epilogue ----
// Tile: BM x BJ of output columns j in [0,1024), computing both halves
// (c at col j, h at col j+1024) of A @ W, then
//   s[m,j] = sp[m,j] + sigmoid(c) * (act(h) - sp[m,j])
// CONCAT: A = concat(xA, xB) over K=2048 (xB = h_prev = Sprev). Else K=1024, Sprev = A.
template <bool CONCAT>
__device__ __noinline__ void gemm_tile(
    const float* __restrict__ xA, const float* __restrict__ xB,
    const float* __restrict__ W, const float* __restrict__ Sprev,
    float* __restrict__ Sout, int act, int tileIdx,
    float (&AsT)[KT][BM + 2], float (&Wcs)[KT][BJ], float (&Whs)[KT][BJ])
{
    const int K = CONCAT ? N2 : HH;
    const int m0 = (tileIdx & 3) * BM;       // 4 m-tiles
    const int j0 = (tileIdx >> 2) * BJ;      // 32 j-tiles
    const int tid = threadIdx.x;

    // A loader: thread -> (row mA, 4 consecutive k), stored transposed [k][m]
    const int mA = tid >> 2;
    const int kq = (tid & 3) << 2;
    // W loader: 128 threads for c-half, 128 for h-half
    const int wHalf = tid >> 7;
    const int wt = tid & 127;
    const int kkW = wt >> 3;
    const int jq = (wt & 7) << 2;
    // Compute map: 16 rowgroups (4 rows each) x 16 colgroups (2 cols each)
    const int r0 = (tid >> 4) << 2;
    const int jj = (tid & 15) << 1;

    u64 accC[2][2] = {{0ULL, 0ULL}, {0ULL, 0ULL}};   // [rowpair][col], lanes = 2 rows
    u64 accH[2][2] = {{0ULL, 0ULL}, {0ULL, 0ULL}};

    auto ldA = [&](int kc) -> float4 {
        int col = kc + kq;
        const float* base = xA;
        int cc = col;
        if (CONCAT && col >= HH) { base = xB; cc = col - HH; }
        return *reinterpret_cast<const float4*>(base + (size_t)(m0 + mA) * HH + cc);
    };
    auto ldW = [&](int kc) -> float4 {
        return *reinterpret_cast<const float4*>(
            W + (size_t)(kc + kkW) * N2 + wHalf * HH + j0 + jq);
    };

    float4 pa = ldA(0);
    float4 pw = ldW(0);

    for (int kc = 0; kc < K; kc += KT) {
        __syncthreads();
        AsT[kq + 0][mA] = pa.x;
        AsT[kq + 1][mA] = pa.y;
        AsT[kq + 2][mA] = pa.z;
        AsT[kq + 3][mA] = pa.w;
        if (wHalf == 0) *reinterpret_cast<float4*>(&Wcs[kkW][jq]) = pw;
        else            *reinterpret_cast<float4*>(&Whs[kkW][jq]) = pw;
        __syncthreads();
        if (kc + KT < K) { pa = ldA(kc + KT); pw = ldW(kc + KT); }

#pragma unroll
        for (int kk = 0; kk < KT; kk++) {
            u64 a01 = *reinterpret_cast<const u64*>(&AsT[kk][r0]);       // rows r0,r0+1
            u64 a23 = *reinterpret_cast<const u64*>(&AsT[kk][r0 + 2]);   // rows r0+2,r0+3
            float2 wc = *reinterpret_cast<const float2*>(&Wcs[kk][jj]);
            float2 wh = *reinterpret_cast<const float2*>(&Whs[kk][jj]);
            u64 wcx = pack2(wc.x), wcy = pack2(wc.y);
            u64 whx = pack2(wh.x), why = pack2(wh.y);
            fma2(accC[0][0], a01, wcx); fma2(accC[1][0], a23, wcx);
            fma2(accC[0][1], a01, wcy); fma2(accC[1][1], a23, wcy);
            fma2(accH[0][0], a01, whx); fma2(accH[1][0], a23, whx);
            fma2(accH[0][1], a01, why); fma2(accH[1][1], a23, why);
        }
    }

#pragma unroll
    for (int p = 0; p < 2; p++) {
        float2 c0 = unpk(accC[p][0]), c1 = unpk(accC[p][1]);
        float2 h0v = unpk(accH[p][0]), h1v = unpk(accH[p][1]);
#pragma unroll
        for (int l = 0; l < 2; l++) {
            int m = m0 + r0 + 2 * p + l;
            float cc0 = l ? c0.y : c0.x;
            float cc1 = l ? c1.y : c1.x;
            float hh0 = l ? h0v.y : h0v.x;
            float hh1 = l ? h1v.y : h1v.x;
            float2 sp = *reinterpret_cast<const float2*>(Sprev + (size_t)m * HH + j0 + jj);
            float s0v = sp.x + sigf(cc0) * (actf(hh0, act) - sp.x);
            float s1v = sp.y + sigf(cc1) * (actf(hh1, act) - sp.y);
            *reinterpret_cast<float2*>(Sout + (size_t)m * HH + j0 + jj) = make_float2(s0v, s1v);
        }
    }
}

// ---- single persistent kernel: all T steps, all ops ----
__global__ __launch_bounds__(NTHR, 2) void darts_persist(
    const float* __restrict__ inputs,  // [T, B, 1024]
    const float* __restrict__ h0,      // [B, 1024]
    const float* __restrict__ W0,      // [2048, 2048]
    const float* __restrict__ Ws,      // [8, 1024, 2048]
    float* __restrict__ out)           // [T, B, 1024]
{
    __shared__ __align__(16) float AsT[KT][BM + 2];
    __shared__ __align__(16) float Wcs[KT][BJ];
    __shared__ __align__(16) float Whs[KT][BJ];

    const int bid = blockIdx.x;
    const size_t WSTR = (size_t)HH * N2;

    for (int t = 0; t < TT; t++) {
        const float* xt = inputs + (size_t)t * BB * HH;
        const float* hp = t ? (out + (size_t)(t - 1) * BB * HH) : h0;

        // Phase A: s0 = h + sig(c0)*(tanh(h0c)-h), K=2048 concat(x, h_prev)
        for (int it = bid; it < 128; it += GBLK)
            gemm_tile<true>(xt, hp, W0, hp, g_S[0], 2, it, AsT, Wcs, Whs);
        gridbar();

        // Phase B: s1 = f(s0, Ws[0], sigmoid)
        for (int it = bid; it < 128; it += GBLK)
            gemm_tile<false>(g_S[0], nullptr, Ws + 0 * WSTR, g_S[0], g_S[1], 0, it, AsT, Wcs, Whs);
        gridbar();

        // Phase C: s2=f(s1,Ws1,relu), s3=f(s1,Ws2,relu), s4=f(s1,Ws3,id)
        for (int it = bid; it < 384; it += GBLK) {
            int op = it >> 7, ti = it & 127;
            gemm_tile<false>(g_S[1], nullptr, Ws + (size_t)(1 + op) * WSTR,
                             g_S[1], g_S[2 + op], (op == 2) ? 3 : 1, ti, AsT, Wcs, Whs);
        }
        gridbar();

        // Phase D: s5=f(s2,Ws4,tanh), s7=f(s3,Ws6,tanh)
        for (int it = bid; it < 256; it += GBLK) {
            int op = it >> 7, ti = it & 127;
            const float* Ap = op ? g_S[3] : g_S[2];
            const float* Wp = Ws + (size_t)(op ? 6 : 4) * WSTR;
            float* Op = op ? g_S[7] : g_S[5];
            gemm_tile<false>(Ap, nullptr, Wp, Ap, Op, 2, ti, AsT, Wcs, Whs);
        }
        gridbar();

        // Phase E: s6=f(s5,Ws5,sigmoid), s8=f(s5,Ws7,relu)
        for (int it = bid; it < 256; it += GBLK) {
            int op = it >> 7, ti = it & 127;
            const float* Wp = Ws + (size_t)(op ? 7 : 5) * WSTR;
            float* Op = op ? g_S[8] : g_S[6];
            gemm_tile<false>(g_S[5], nullptr, Wp, g_S[5], Op, op ? 1 : 0, ti, AsT, Wcs, Whs);
        }
        gridbar();

        // Phase F: out[t] = mean(s1..s8)
        {
            float* ot = out + (size_t)t * BB * HH;
            for (int i = bid * NTHR + threadIdx.x; i < BB * HH / 4; i += GBLK * NTHR) {
                float4 s = make_float4(0.f, 0.f, 0.f, 0.f);
#pragma unroll
                for (int b = 1; b < 9; b++) {
                    float4 v = reinterpret_cast<const float4*>(g_S[b])[i];
                    s.x += v.x; s.y += v.y; s.z += v.z; s.w += v.w;
                }
                reinterpret_cast<float4*>(ot)[i] =
                    make_float4(s.x * 0.125f, s.y * 0.125f, s.z * 0.125f, s.w * 0.125f);
            }
        }
        gridbar();
    }
}

extern "C" void kernel_launch(void* const* d_in, const int* in_sizes, int n_in,
                              void* d_out, int out_size)
{
    const float* inputs = (const float*)d_in[0];  // [T, B, 1024]
    const float* h0     = (const float*)d_in[1];  // [B, 1024]
    const float* W0     = (const float*)d_in[2];  // [2048, 2048]
    const float* Ws     = (const float*)d_in[3];  // [8, 1024, 2048]
    float* out = (float*)d_out;                   // [T, B, 1024]

    darts_persist<<<GBLK, NTHR>>>(inputs, h0, W0, Ws, out);
}

// round 10
// speedup vs baseline: 3.1169x; 3.0414x over previous
#include <cuda_runtime.h>
#include <cuda_bf16.h>
#include <math.h>
#include <stdint.h>

typedef uint32_t u32;
typedef unsigned long long u64;

#define TT 256
#define BB 256
#define HH 1024
#define N2 2048
#define BMH (BB*HH)
#define NTHR 256
#define GBLK 128
#define CHU 1024                 /* uint4 per 16KB image block */
#define PPL (256*2048)           /* floats per partial plane */
#define SMEMT 131072             /* 2 x 64KB chunk buffers */
#define SWZ(o) ((o) ^ (((o) >> 3) & 0x70))

/* fp32 states s0..s8 (6 and 8 unused but kept for indexing) */
__device__ float g_S[9][BMH];
/* split-K fp32 partials: [slot<=3][split<=4][256][2048] */
__device__ float g_P[3 * 4 * PPL];
/* bf16 hi/lo swizzled images: states [st][mt][kc], x/h [mt][kc], W0 [nt][kc], Ws [op][nt][kc] */
__device__ uint4 g_Sih[288 * CHU], g_Sil[288 * CHU];
__device__ uint4 g_Xh[32 * CHU],  g_Xl[32 * CHU];
__device__ uint4 g_Hh[32 * CHU],  g_Hl[32 * CHU];
__device__ uint4 g_W0h[512 * CHU], g_W0l[512 * CHU];
__device__ uint4 g_Wsh[2048 * CHU], g_Wsl[2048 * CHU];
__device__ u64 g_bar;

/* ---------------- helpers ---------------- */
__device__ __forceinline__ float sigf(float v) { return 1.0f / (1.0f + expf(-v)); }
__device__ __forceinline__ float actf(float v, int a) {
    switch (a) { case 0: return sigf(v); case 1: return fmaxf(v, 0.0f);
                 case 2: return tanhf(v); default: return v; }
}
__device__ __forceinline__ u32 smem_u32(const void* p) {
    u32 a; asm("{ .reg .u64 t; cvta.to.shared.u64 t, %1; cvt.u32.u64 %0, t; }" : "=r"(a) : "l"(p));
    return a;
}
/* 8 fp32 -> bf16 hi + bf16 lo (residual), packed uint4 each */
__device__ __forceinline__ void split8(const float* v, uint4& hi, uint4& lo) {
    u32 h[4], l[4];
#pragma unroll
    for (int p = 0; p < 4; p++) {
        __nv_bfloat16 b0 = __float2bfloat16(v[2*p]);
        __nv_bfloat16 b1 = __float2bfloat16(v[2*p+1]);
        __nv_bfloat16 c0 = __float2bfloat16(v[2*p]   - __bfloat162float(b0));
        __nv_bfloat16 c1 = __float2bfloat16(v[2*p+1] - __bfloat162float(b1));
        h[p] = (u32)__bfloat16_as_ushort(b0) | ((u32)__bfloat16_as_ushort(b1) << 16);
        l[p] = (u32)__bfloat16_as_ushort(c0) | ((u32)__bfloat16_as_ushort(c1) << 16);
    }
    hi = make_uint4(h[0], h[1], h[2], h[3]);
    lo = make_uint4(l[0], l[1], l[2], l[3]);
}

/* ---------------- warp MMA primitives (base-target safe) ---------------- */
__device__ __forceinline__ void ldsm4(u32* d, u32 a) {
    asm volatile("ldmatrix.sync.aligned.m8n8.x4.shared.b16 {%0,%1,%2,%3}, [%4];"
        : "=r"(d[0]), "=r"(d[1]), "=r"(d[2]), "=r"(d[3]) : "r"(a));
}
__device__ __forceinline__ void ldsm2(u32* d, u32 a) {
    asm volatile("ldmatrix.sync.aligned.m8n8.x2.shared.b16 {%0,%1}, [%2];"
        : "=r"(d[0]), "=r"(d[1]) : "r"(a));
}
__device__ __forceinline__ void mma16816(float* c, const u32* a, const u32* b) {
    asm volatile("mma.sync.aligned.m16n8k16.row.col.f32.bf16.bf16.f32 "
        "{%0,%1,%2,%3}, {%4,%5,%6,%7}, {%8,%9}, {%0,%1,%2,%3};"
        : "+f"(c[0]), "+f"(c[1]), "+f"(c[2]), "+f"(c[3])
        : "r"(a[0]), "r"(a[1]), "r"(a[2]), "r"(a[3]), "r"(b[0]), "r"(b[1]));
}
#define CPA(dst, src) asm volatile("cp.async.cg.shared.global [%0], [%1], 16;" :: "r"(dst), "l"(src))
#define CPCOMMIT()    asm volatile("cp.async.commit_group;" ::: "memory")
#define CPWAIT(n)     asm volatile("cp.async.wait_group %0;" :: "n"(n) : "memory")

/* ---------------- grid barrier (monotonic, replay-safe) ---------------- */
__device__ __forceinline__ void gridbar() {
    __threadfence();
    __syncthreads();
    if (threadIdx.x == 0) {
        u64 t = atomicAdd(&g_bar, 1ULL);
        u64 goal = (t / GBLK + 1ULL) * (u64)GBLK;
        u64 v;
        do { asm volatile("ld.acquire.gpu.u64 %0, [%1];" : "=l"(v) : "l"(&g_bar) : "memory"); }
        while (v < goal);
    }
    __syncthreads();
}

/* ---------------- prep: build swizzled bf16 hi/lo images ---------------- */
__global__ __launch_bounds__(NTHR) void prep(
    const float* __restrict__ inputs, const float* __restrict__ h0,
    const float* __restrict__ W0, const float* __restrict__ Ws)
{
    __shared__ float s[64][129];
    const int b = blockIdx.x, tid = threadIdx.x;

    if (b < 2560) {
        const float* Wsrc; int nt, kc; uint4 *dh, *dl;
        if (b < 512) {
            nt = b >> 5; kc = b & 31; Wsrc = W0;
            dh = g_W0h + (size_t)b * CHU; dl = g_W0l + (size_t)b * CHU;
        } else {
            int b2 = b - 512;
            int op = b2 >> 8; nt = (b2 >> 4) & 15; kc = b2 & 15;
            (void)op;
            Wsrc = Ws + (size_t)(b2 >> 8) * HH * N2;
            dh = g_Wsh + (size_t)b2 * CHU; dl = g_Wsl + (size_t)b2 * CHU;
        }
        for (int i = tid; i < 64 * 128; i += NTHR) {
            int k = i >> 7, r = i & 127;
            int n = (r < 64) ? nt * 64 + r : HH + nt * 64 + (r - 64);
            s[k][r] = Wsrc[(size_t)(kc * 64 + k) * N2 + n];
        }
        __syncthreads();
        for (int uu = tid; uu < 1024; uu += NTHR) {
            int r = uu >> 3, g = uu & 7;
            float v[8];
#pragma unroll
            for (int i = 0; i < 8; i++) v[i] = s[g * 8 + i][r];
            uint4 hi, lo; split8(v, hi, lo);
            u32 off = SWZ((u32)(r * 128 + g * 16));
            dh[off >> 4] = hi; dl[off >> 4] = lo;
        }
    } else {
        int b3 = b - 2560;
        const float* src = (b3 < 128) ? inputs : h0;
        uint4* dh = (b3 < 128) ? g_Xh : g_Hh;
        uint4* dl = (b3 < 128) ? g_Xl : g_Hl;
        int uu = (b3 & 127) * NTHR + tid;
        int g = uu & 7, r = (uu >> 3) & 127, kc = (uu >> 10) & 15, mt = uu >> 14;
        int m = mt * 128 + r, k = kc * 64 + g * 8;
        const float4* p = (const float4*)(src + (size_t)m * HH + k);
        float4 a = p[0], bq = p[1];
        float v[8] = {a.x, a.y, a.z, a.w, bq.x, bq.y, bq.z, bq.w};
        uint4 hi, lo; split8(v, hi, lo);
        u32 off = SWZ((u32)(r * 128 + g * 16));
        size_t blk = (size_t)(mt * 16 + kc) * CHU;
        dh[blk + (off >> 4)] = hi; dl[blk + (off >> 4)] = lo;
    }
}

/* ---------------- split-K GEMM task: M128 x N128(=64c||64h), chunks [c0,c0+cs) ----------------
 * Warp layout: 8 warps = 2(M64) x 4(N32). mma.sync m16n8k16 bf16, 3-pass hi/lo compensation.
 * Writes fp32 partial plane Pout[m][nt*128 + jn]. */
__device__ __noinline__ void run_gemm(u32 sbase,
    const uint4* __restrict__ Ah0, const uint4* __restrict__ Al0,
    const uint4* __restrict__ Ah1, const uint4* __restrict__ Al1, int n1,
    const uint4* __restrict__ Bh, const uint4* __restrict__ Bl,
    int c0, int cs, float* __restrict__ Pout, int m0base, int ntile)
{
    const int tid = threadIdx.x, lid = tid & 31, wid = tid >> 5;
    const int wm = wid >> 2, wn = wid & 3;

    float acc[4][4][4];
#pragma unroll
    for (int i = 0; i < 4; i++)
#pragma unroll
        for (int j = 0; j < 4; j++)
#pragma unroll
            for (int q = 0; q < 4; q++) acc[i][j][q] = 0.f;

    const int raRow = wm * 64 + (lid & 7) + ((lid >> 3) & 1) * 8;
    const u32 raXor = (u32)((lid & 7) << 4);
    const u32 koffA = (u32)((lid >> 4) * 16);
    const int lb = lid & 15;
    const int rbRow = wn * 32 + (lb & 7);
    const u32 rbXor = (u32)((lb & 7) << 4);
    const u32 koffB = (u32)(((lb >> 3) & 1) * 16);

    auto issue = [&](int ci, int buf) {
        int c = c0 + ci;
        const uint4* sAh = (c < n1) ? (Ah0 + (size_t)c * CHU) : (Ah1 + (size_t)(c - n1) * CHU);
        const uint4* sAl = (c < n1) ? (Al0 + (size_t)c * CHU) : (Al1 + (size_t)(c - n1) * CHU);
        const uint4* sBh = Bh + (size_t)c * CHU;
        const uint4* sBl = Bl + (size_t)c * CHU;
        u32 d = sbase + (u32)buf * 65536u + (u32)tid * 16u;
#pragma unroll
        for (int i = 0; i < 4; i++) {
            u32 off = (u32)i * 4096u;
            CPA(d + off,         (const void*)(sAh + tid + i * 256));
            CPA(d + 16384 + off, (const void*)(sAl + tid + i * 256));
            CPA(d + 32768 + off, (const void*)(sBh + tid + i * 256));
            CPA(d + 49152 + off, (const void*)(sBl + tid + i * 256));
        }
        CPCOMMIT();
    };

    issue(0, 0);
    if (cs > 1) issue(1, 1);
    int buf = 0;
    for (int ci = 0; ci < cs; ci++) {
        if (ci < cs - 1) { CPWAIT(1); } else { CPWAIT(0); }
        __syncthreads();
        u32 b0 = sbase + (u32)buf * 65536u;
#pragma unroll
        for (int ks = 0; ks < 4; ks++) {
            u32 ah[4][4], al[4][4], bhf[4][2], blf[4][2];
            u32 ka = ((u32)(ks * 32) + koffA) ^ raXor;
#pragma unroll
            for (int mt = 0; mt < 4; mt++) {
                u32 ad = b0 + (u32)((raRow + mt * 16) * 128) + ka;
                ldsm4(ah[mt], ad);
                ldsm4(al[mt], ad + 16384);
            }
            u32 kb = ((u32)(ks * 32) + koffB) ^ rbXor;
#pragma unroll
            for (int nt = 0; nt < 4; nt++) {
                u32 bd = b0 + 32768 + (u32)((rbRow + nt * 8) * 128) + kb;
                ldsm2(bhf[nt], bd);
                ldsm2(blf[nt], bd + 16384);
            }
#pragma unroll
            for (int mt = 0; mt < 4; mt++)
#pragma unroll
                for (int nt = 0; nt < 4; nt++) {
                    mma16816(acc[mt][nt], ah[mt], bhf[nt]);
                    mma16816(acc[mt][nt], ah[mt], blf[nt]);
                    mma16816(acc[mt][nt], al[mt], bhf[nt]);
                }
        }
        __syncthreads();
        if (ci + 2 < cs) issue(ci + 2, buf);
        buf ^= 1;
    }

#pragma unroll
    for (int mt = 0; mt < 4; mt++) {
        int m = m0base + wm * 64 + mt * 16 + (lid >> 2);
#pragma unroll
        for (int nt = 0; nt < 4; nt++) {
            int jc = ntile * 128 + wn * 32 + nt * 8 + (lid & 3) * 2;
            float* p = Pout + (size_t)m * 2048 + jc;
            *(float2*)p = make_float2(acc[mt][nt][0], acc[mt][nt][1]);
            *(float2*)(p + (size_t)8 * 2048) = make_float2(acc[mt][nt][2], acc[mt][nt][3]);
        }
    }
}

/* ---------------- epilogue: reduce splits, apply gates, 8 outputs per call ---------------- */
__device__ __forceinline__ void epi8(int m, int j, const float* __restrict__ P, int nsplit,
                                     const float* __restrict__ sp, int act, float* o)
{
    int nt = j >> 6, r = j & 63;
    const float* b = P + (size_t)m * 2048 + nt * 128 + r;
    float c[8], h[8];
#pragma unroll
    for (int i = 0; i < 8; i++) { c[i] = 0.f; h[i] = 0.f; }
    for (int s = 0; s < nsplit; s++) {
        const float* ps = b + (size_t)s * PPL;
        float4 x0 = ((const float4*)ps)[0], x1 = ((const float4*)ps)[1];
        float4 y0 = ((const float4*)(ps + 64))[0], y1 = ((const float4*)(ps + 64))[1];
        c[0] += x0.x; c[1] += x0.y; c[2] += x0.z; c[3] += x0.w;
        c[4] += x1.x; c[5] += x1.y; c[6] += x1.z; c[7] += x1.w;
        h[0] += y0.x; h[1] += y0.y; h[2] += y0.z; h[3] += y0.w;
        h[4] += y1.x; h[5] += y1.y; h[6] += y1.z; h[7] += y1.w;
    }
    const float4* pp = (const float4*)(sp + (size_t)m * HH + j);
    float4 p0 = pp[0], p1 = pp[1];
    float pv[8] = {p0.x, p0.y, p0.z, p0.w, p1.x, p1.y, p1.z, p1.w};
#pragma unroll
    for (int q = 0; q < 8; q++) o[q] = pv[q] + sigf(c[q]) * (actf(h[q], act) - pv[q]);
}

__device__ __forceinline__ void st_state(int m, int j, const float* o,
    float* __restrict__ sfp, uint4* __restrict__ iH, uint4* __restrict__ iL)
{
    float4* q = (float4*)(sfp + (size_t)m * HH + j);
    q[0] = make_float4(o[0], o[1], o[2], o[3]);
    q[1] = make_float4(o[4], o[5], o[6], o[7]);
    if (iH) {
        uint4 hi, lo; split8(o, hi, lo);
        u32 off = SWZ((u32)((m & 127) * 128 + (j & 63) * 2));
        size_t blk = ((size_t)(m >> 7) * 16 + (j >> 6)) * CHU;
        iH[blk + (off >> 4)] = hi; iL[blk + (off >> 4)] = lo;
    }
}

/* ---------------- persistent kernel: all steps & phases ---------------- */
__global__ __launch_bounds__(NTHR, 1) void darts_mma(
    const float* __restrict__ inputs, const float* __restrict__ h0,
    float* __restrict__ out)
{
    extern __shared__ char smem[];
    const u32 sbase = smem_u32(smem);
    const int tid = threadIdx.x, bid = blockIdx.x;

    for (int t = 0; t < TT; t++) {
        const float* hp = t ? (out + (size_t)(t - 1) * BMH) : h0;

        /* A-GEMM: s0 partials, K=2048 over concat(x, h). 128 tasks = 32 tiles x 4 splits */
        {
            int split = bid & 3, tile = bid >> 2, mt = tile & 1, nt = tile >> 1;
            run_gemm(sbase,
                g_Xh + (size_t)mt * 16 * CHU, g_Xl + (size_t)mt * 16 * CHU,
                g_Hh + (size_t)mt * 16 * CHU, g_Hl + (size_t)mt * 16 * CHU, 16,
                g_W0h + (size_t)nt * 32 * CHU, g_W0l + (size_t)nt * 32 * CHU,
                split * 8, 8, g_P + (size_t)split * PPL, mt * 128, nt);
        }
        gridbar();
        /* A-epi: s0 = h + sig(c)*(tanh(h0c)-h), fp32 + image */
        {
            int uu = bid * NTHR + tid;
            int m = uu >> 7, j = (uu & 127) * 8;
            float o[8];
            epi8(m, j, g_P, 4, hp, 2, o);
            st_state(m, j, o, g_S[0], g_Sih, g_Sil);
        }
        gridbar();

        /* B-GEMM: s1 partials from s0 image */
        {
            int split = bid & 3, tile = bid >> 2, mt = tile & 1, nt = tile >> 1;
            run_gemm(sbase,
                g_Sih + (size_t)(0 * 32 + mt * 16) * CHU, g_Sil + (size_t)(0 * 32 + mt * 16) * CHU,
                (const uint4*)0, (const uint4*)0, 16,
                g_Wsh + (size_t)(0 * 256 + nt * 16) * CHU, g_Wsl + (size_t)(0 * 256 + nt * 16) * CHU,
                split * 4, 4, g_P + (size_t)split * PPL, mt * 128, nt);
        }
        gridbar();
        /* B-epi: s1 sigmoid, fp32 + image */
        {
            int uu = bid * NTHR + tid;
            int m = uu >> 7, j = (uu & 127) * 8;
            float o[8];
            epi8(m, j, g_P, 4, g_S[0], 0, o);
            st_state(m, j, o, g_S[1], g_Sih + (size_t)1 * 32 * CHU, g_Sil + (size_t)1 * 32 * CHU);
        }
        gridbar();

        /* C-GEMM: s2,s3,s4 partials from s1 image; 3 waves, slot q */
        for (int q = 0; q < 3; q++) {
            int split = bid & 3, tile = bid >> 2, mt = tile & 1, nt = tile >> 1;
            run_gemm(sbase,
                g_Sih + (size_t)(1 * 32 + mt * 16) * CHU, g_Sil + (size_t)(1 * 32 + mt * 16) * CHU,
                (const uint4*)0, (const uint4*)0, 16,
                g_Wsh + (size_t)((1 + q) * 256 + nt * 16) * CHU,
                g_Wsl + (size_t)((1 + q) * 256 + nt * 16) * CHU,
                split * 4, 4, g_P + (size_t)(q * 4 + split) * PPL, mt * 128, nt);
        }
        gridbar();
        /* C-epi: s2(relu,img), s3(relu,img), s4(identity) */
        {
            int uu = bid * NTHR + tid;
            int m = uu >> 7, j = (uu & 127) * 8;
            float o[8];
            epi8(m, j, g_P, 4, g_S[1], 1, o);
            st_state(m, j, o, g_S[2], g_Sih + (size_t)2 * 32 * CHU, g_Sil + (size_t)2 * 32 * CHU);
            epi8(m, j, g_P + (size_t)4 * PPL, 4, g_S[1], 1, o);
            st_state(m, j, o, g_S[3], g_Sih + (size_t)3 * 32 * CHU, g_Sil + (size_t)3 * 32 * CHU);
            epi8(m, j, g_P + (size_t)8 * PPL, 4, g_S[1], 3, o);
            st_state(m, j, o, g_S[4], (uint4*)0, (uint4*)0);
        }
        gridbar();

        /* D-GEMM: s5<-s2 (op0), s7<-s3 (op1); 2 ops x 32 tiles x 2 splits */
        {
            int split = bid & 1, tile = (bid >> 1) & 31, op = bid >> 6;
            int mt = tile & 1, nt = tile >> 1;
            int ins = op ? 3 : 2, wop = op ? 6 : 4;
            run_gemm(sbase,
                g_Sih + (size_t)(ins * 32 + mt * 16) * CHU, g_Sil + (size_t)(ins * 32 + mt * 16) * CHU,
                (const uint4*)0, (const uint4*)0, 16,
                g_Wsh + (size_t)(wop * 256 + nt * 16) * CHU, g_Wsl + (size_t)(wop * 256 + nt * 16) * CHU,
                split * 8, 8, g_P + (size_t)(op * 4 + split) * PPL, mt * 128, nt);
        }
        gridbar();
        /* D-epi: s5 (tanh, img), s7 (tanh) */
        {
            int uu = bid * NTHR + tid;
            int m = uu >> 7, j = (uu & 127) * 8;
            float o[8];
            epi8(m, j, g_P, 2, g_S[2], 2, o);
            st_state(m, j, o, g_S[5], g_Sih + (size_t)5 * 32 * CHU, g_Sil + (size_t)5 * 32 * CHU);
            epi8(m, j, g_P + (size_t)4 * PPL, 2, g_S[3], 2, o);
            st_state(m, j, o, g_S[7], (uint4*)0, (uint4*)0);
        }
        gridbar();

        /* E-GEMM: s6<-s5 (op0, W5), s8<-s5 (op1, W7) */
        {
            int split = bid & 1, tile = (bid >> 1) & 31, op = bid >> 6;
            int mt = tile & 1, nt = tile >> 1;
            int wop = op ? 7 : 5;
            run_gemm(sbase,
                g_Sih + (size_t)(5 * 32 + mt * 16) * CHU, g_Sil + (size_t)(5 * 32 + mt * 16) * CHU,
                (const uint4*)0, (const uint4*)0, 16,
                g_Wsh + (size_t)(wop * 256 + nt * 16) * CHU, g_Wsl + (size_t)(wop * 256 + nt * 16) * CHU,
                split * 8, 8, g_P + (size_t)(op * 4 + split) * PPL, mt * 128, nt);
        }
        gridbar();
        /* E-epi + F: s6, s8 in-reg; out[t] = mean(s1..s8); emit h image; convert x_{t+1} */
        {
            int uu = bid * NTHR + tid;
            int m = uu >> 7, j = (uu & 127) * 8;
            float s6v[8], s8v[8], a[8];
            epi8(m, j, g_P, 2, g_S[5], 0, s6v);
            epi8(m, j, g_P + (size_t)4 * PPL, 2, g_S[5], 1, s8v);
#pragma unroll
            for (int q = 0; q < 8; q++) a[q] = s6v[q] + s8v[q];
            const int sts[6] = {1, 2, 3, 4, 5, 7};
#pragma unroll
            for (int si = 0; si < 6; si++) {
                const float4* p = (const float4*)(&g_S[sts[si]][(size_t)m * HH + j]);
                float4 v0 = p[0], v1 = p[1];
                a[0] += v0.x; a[1] += v0.y; a[2] += v0.z; a[3] += v0.w;
                a[4] += v1.x; a[5] += v1.y; a[6] += v1.z; a[7] += v1.w;
            }
#pragma unroll
            for (int q = 0; q < 8; q++) a[q] *= 0.125f;
            float* ot = out + (size_t)t * BMH;
            float4* q4 = (float4*)(ot + (size_t)m * HH + j);
            q4[0] = make_float4(a[0], a[1], a[2], a[3]);
            q4[1] = make_float4(a[4], a[5], a[6], a[7]);
            {
                uint4 hi, lo; split8(a, hi, lo);
                u32 off = SWZ((u32)((m & 127) * 128 + (j & 63) * 2));
                size_t blk = ((size_t)(m >> 7) * 16 + (j >> 6)) * CHU;
                g_Hh[blk + (off >> 4)] = hi; g_Hl[blk + (off >> 4)] = lo;
            }
            if (t + 1 < TT) {
                const float4* p = (const float4*)(inputs + (size_t)(t + 1) * BMH + (size_t)m * HH + j);
                float4 v0 = p[0], v1 = p[1];
                float v[8] = {v0.x, v0.y, v0.z, v0.w, v1.x, v1.y, v1.z, v1.w};
                uint4 hi, lo; split8(v, hi, lo);
                u32 off = SWZ((u32)((m & 127) * 128 + (j & 63) * 2));
                size_t blk = ((size_t)(m >> 7) * 16 + (j >> 6)) * CHU;
                g_Xh[blk + (off >> 4)] = hi; g_Xl[blk + (off >> 4)] = lo;
            }
        }
        gridbar();
    }
}

extern "C" void kernel_launch(void* const* d_in, const int* in_sizes, int n_in,
                              void* d_out, int out_size)
{
    const float* inputs = (const float*)d_in[0];  /* [T, B, 1024] */
    const float* h0     = (const float*)d_in[1];  /* [B, 1024]    */
    const float* W0     = (const float*)d_in[2];  /* [2048, 2048] */
    const float* Ws     = (const float*)d_in[3];  /* [8, 1024, 2048] */
    float* out = (float*)d_out;                   /* [T, B, 1024] */

    cudaFuncSetAttribute(darts_mma, cudaFuncAttributeMaxDynamicSharedMemorySize, SMEMT);

    prep<<<2816, NTHR>>>(inputs, h0, W0, Ws);
    darts_mma<<<GBLK, NTHR, SMEMT>>>(inputs, h0, out);
}